// round 4
// baseline (speedup 1.0000x reference)
#include <cuda_runtime.h>
#include <cuda_fp16.h>
#include <math.h>

#define NN 50000
#define NE 800000
#define NET (NE + NN)
#define NG 256
#define NB ((NN + 255) / 256)

// ---------------- device scratch ------------------------------------------
__device__ __half   g_h1[NN * 64];
__device__ float    g_ssrc1[NN * 4];
__device__ float    g_sdst1[NN * 4];
__device__ float    g_mx1[NN * 4];
__device__ float    g_inv1[NN * 4];
__device__ float    g_out1[NN * 64];
__device__ __half   g_h2[NN * 256];
__device__ float    g_ssrc2[NN];
__device__ float    g_sdst2[NN];
__device__ float    g_mx2[NN];
__device__ float    g_inv2[NN];
__device__ float    g_out2[NN * 256];
__device__ int      g_counts[NN];
__device__ int      g_offsets[NN + 1];
__device__ int      g_bsums[NB];
__device__ int      g_epos[NET];
__device__ int      g_csr_src[NET];
__device__ float    g_poolf[NG * 256];
__device__ float    g_z1[NG * 512];
__device__ float    g_z2[NG * 1024];

// ---------------- helpers --------------------------------------------------
__device__ __forceinline__ float leaky(float x) { return x > 0.f ? x : 0.2f * x; }
__device__ __forceinline__ float elu(float x)   { return x > 0.f ? x : expm1f(x); }

// ---------------- prep -----------------------------------------------------
__global__ void zero_kernel() {
    int i = blockIdx.x * blockDim.x + threadIdx.x;
    if (i < NN) g_counts[i] = 0;
}

// histogram + record intra-bucket position (so scatter needs no atomics)
__global__ void hist_kernel(const int* __restrict__ ei) {
    int e = blockIdx.x * blockDim.x + threadIdx.x;
    if (e >= NET) return;
    int dst = (e < NE) ? ei[NE + e] : (e - NE);
    g_epos[e] = atomicAdd(&g_counts[dst], 1);
}

__global__ void bsum_kernel() {
    __shared__ int ws[8];
    int i = blockIdx.x * 256 + threadIdx.x;
    int v = (i < NN) ? g_counts[i] : 0;
    #pragma unroll
    for (int off = 16; off; off >>= 1) v += __shfl_xor_sync(0xffffffffu, v, off);
    int lane = threadIdx.x & 31, wid = threadIdx.x >> 5;
    if (lane == 0) ws[wid] = v;
    __syncthreads();
    if (threadIdx.x == 0) {
        int s = 0;
        #pragma unroll
        for (int w = 0; w < 8; w++) s += ws[w];
        g_bsums[blockIdx.x] = s;
    }
}

__global__ void bscan_kernel() {
    __shared__ int wsum[8];
    int t = threadIdx.x, lane = t & 31, wid = t >> 5;
    int v = (t < NB) ? g_bsums[t] : 0;
    int s = v;
    #pragma unroll
    for (int off = 1; off < 32; off <<= 1) {
        int u = __shfl_up_sync(0xffffffffu, s, off);
        if (lane >= off) s += u;
    }
    if (lane == 31) wsum[wid] = s;
    __syncthreads();
    if (wid == 0 && lane < 8) {
        int ws = wsum[lane];
        #pragma unroll
        for (int off = 1; off < 8; off <<= 1) {
            int u = __shfl_up_sync(0xffu, ws, off);
            if (lane >= off) ws += u;
        }
        wsum[lane] = ws;
    }
    __syncthreads();
    int pre = (wid > 0) ? wsum[wid - 1] : 0;
    if (t < NB) g_bsums[t] = pre + s - v;
}

__global__ void offs_kernel() {
    __shared__ int wsum[8];
    int t = threadIdx.x, lane = t & 31, wid = t >> 5;
    int i = blockIdx.x * 256 + t;
    int v = (i < NN) ? g_counts[i] : 0;
    int s = v;
    #pragma unroll
    for (int off = 1; off < 32; off <<= 1) {
        int u = __shfl_up_sync(0xffffffffu, s, off);
        if (lane >= off) s += u;
    }
    if (lane == 31) wsum[wid] = s;
    __syncthreads();
    if (wid == 0 && lane < 8) {
        int ws = wsum[lane];
        #pragma unroll
        for (int off = 1; off < 8; off <<= 1) {
            int u = __shfl_up_sync(0xffu, ws, off);
            if (lane >= off) ws += u;
        }
        wsum[lane] = ws;
    }
    __syncthreads();
    int pre = (wid > 0) ? wsum[wid - 1] : 0;
    if (i < NN) g_offsets[i] = g_bsums[blockIdx.x] + pre + s - v;
    if (i == 0) g_offsets[NN] = NET;
}

__global__ void scatter_kernel(const int* __restrict__ ei) {
    int e = blockIdx.x * blockDim.x + threadIdx.x;
    if (e >= NET) return;
    int src, dst;
    if (e < NE) { src = ei[e]; dst = ei[NE + e]; }
    else        { src = dst = e - NE; }
    g_csr_src[g_offsets[dst] + g_epos[e]] = src;
}

// ---------------- GAT layer 1 ----------------------------------------------
// h1 = x @ W1 (fp16 store), fused s1. 4 nodes / 256-thread block.
__global__ void gemm1_kernel(const float* __restrict__ x, const float* __restrict__ W1,
                             const float* __restrict__ a_src, const float* __restrict__ a_dst) {
    __shared__ float sx[4][28];
    int nodeBase = blockIdx.x * 4;
    int tid = threadIdx.x;
    if (tid < 4 * 27) {
        int n = tid / 27, c = tid - n * 27;
        sx[n][c] = x[(nodeBase + n) * 27 + c];
    }
    __syncthreads();
    int n = tid >> 6, j = tid & 63;
    float acc = 0.f;
    #pragma unroll
    for (int k = 0; k < 27; k++) acc += sx[n][k] * W1[k * 64 + j];
    g_h1[(nodeBase + n) * 64 + j] = __float2half_rn(acc);
    float ps = acc * a_src[j];
    float pd = acc * a_dst[j];
    #pragma unroll
    for (int off = 8; off; off >>= 1) {
        ps += __shfl_xor_sync(0xffffffffu, ps, off);
        pd += __shfl_xor_sync(0xffffffffu, pd, off);
    }
    if ((j & 15) == 0) {
        int h = j >> 4;
        g_ssrc1[(nodeBase + n) * 4 + h] = ps;
        g_sdst1[(nodeBase + n) * 4 + h] = pd;
    }
}

// single-pass online-softmax stats: warp per node -> (mx, inv) per (node, head)
template <int H>
__global__ void stats_kernel(const float* __restrict__ ssrc, const float* __restrict__ sdst,
                             float* __restrict__ gmx, float* __restrict__ ginv) {
    int node = blockIdx.x * 8 + (threadIdx.x >> 5);
    if (node >= NN) return;
    int lane = threadIdx.x & 31;
    int beg = g_offsets[node], end = g_offsets[node + 1];
    float sd[H], mx[H], den[H];
    #pragma unroll
    for (int h = 0; h < H; h++) { sd[h] = sdst[node * H + h]; mx[h] = -3.4e38f; den[h] = 0.f; }
    for (int i = beg + lane; i < end; i += 32) {
        int s = g_csr_src[i];
        if (H == 4) {
            float4 sv = *(const float4*)(ssrc + s * 4);
            float v[4] = { leaky(sv.x + sd[0]), leaky(sv.y + sd[1]),
                           leaky(sv.z + sd[2]), leaky(sv.w + sd[3]) };
            #pragma unroll
            for (int h = 0; h < 4; h++) {
                float nm = fmaxf(mx[h], v[h]);
                den[h] = den[h] * __expf(mx[h] - nm) + __expf(v[h] - nm);
                mx[h] = nm;
            }
        } else {
            float v = leaky(ssrc[s] + sd[0]);
            float nm = fmaxf(mx[0], v);
            den[0] = den[0] * __expf(mx[0] - nm) + __expf(v - nm);
            mx[0] = nm;
        }
    }
    #pragma unroll
    for (int h = 0; h < H; h++) {
        #pragma unroll
        for (int off = 16; off; off >>= 1) {
            float omx = __shfl_xor_sync(0xffffffffu, mx[h], off);
            float ode = __shfl_xor_sync(0xffffffffu, den[h], off);
            float nm = fmaxf(mx[h], omx);
            den[h] = den[h] * __expf(mx[h] - nm) + ode * __expf(omx - nm);
            mx[h] = nm;
        }
    }
    if (lane == 0) {
        #pragma unroll
        for (int h = 0; h < H; h++) {
            gmx[node * H + h] = mx[h];
            ginv[node * H + h] = 1.f / (den[h] + 1e-16f);
        }
    }
}

// agg1: 8 threads/node (8 fp16 ch each), weight recomputed inline, 2-edge unroll
__global__ void agg1_kernel(const float* __restrict__ b1) {
    int node = blockIdx.x * 32 + (threadIdx.x >> 3);
    if (node >= NN) return;
    int t = threadIdx.x & 7;          // ch = 8t .. 8t+7
    int h = t >> 1;
    float sd = g_sdst1[node * 4 + h];
    float mx = g_mx1[node * 4 + h];
    float accA[8], accB[8];
    #pragma unroll
    for (int c = 0; c < 8; c++) { accA[c] = 0.f; accB[c] = 0.f; }
    int beg = g_offsets[node], end = g_offsets[node + 1];
    const __half* h1 = g_h1;
    int i = beg;
    for (; i + 1 < end; i += 2) {
        int s0 = g_csr_src[i], s1 = g_csr_src[i + 1];
        float w0 = __expf(leaky(g_ssrc1[s0 * 4 + h] + sd) - mx);
        float w1 = __expf(leaky(g_ssrc1[s1 * 4 + h] + sd) - mx);
        uint4 r0 = *(const uint4*)(h1 + s0 * 64 + t * 8);
        uint4 r1 = *(const uint4*)(h1 + s1 * 64 + t * 8);
        const __half2* p0 = (const __half2*)&r0;
        const __half2* p1 = (const __half2*)&r1;
        #pragma unroll
        for (int c = 0; c < 4; c++) {
            float2 v0 = __half22float2(p0[c]);
            float2 v1 = __half22float2(p1[c]);
            accA[2 * c]     += w0 * v0.x;  accA[2 * c + 1] += w0 * v0.y;
            accB[2 * c]     += w1 * v1.x;  accB[2 * c + 1] += w1 * v1.y;
        }
    }
    if (i < end) {
        int s0 = g_csr_src[i];
        float w0 = __expf(leaky(g_ssrc1[s0 * 4 + h] + sd) - mx);
        uint4 r0 = *(const uint4*)(h1 + s0 * 64 + t * 8);
        const __half2* p0 = (const __half2*)&r0;
        #pragma unroll
        for (int c = 0; c < 4; c++) {
            float2 v0 = __half22float2(p0[c]);
            accA[2 * c]     += w0 * v0.x;  accA[2 * c + 1] += w0 * v0.y;
        }
    }
    float inv = g_inv1[node * 4 + h];
    #pragma unroll
    for (int c = 0; c < 8; c++)
        g_out1[node * 64 + t * 8 + c] = elu((accA[c] + accB[c]) * inv + b1[t * 8 + c]);
}

// ---------------- GAT layer 2 ----------------------------------------------
// h2 = out1 @ W2 -> fp16; s2 fused. 32 rows / 256-thread block.
__global__ void gemm2_kernel(const float* __restrict__ W2,
                             const float* __restrict__ a_src, const float* __restrict__ a_dst) {
    __shared__ float sA[32][64];
    __shared__ float sred[8][32][2];
    int nodeBase = blockIdx.x * 32;
    int tid = threadIdx.x;
    for (int t = tid; t < 32 * 64; t += 256) {
        int r = t >> 6, c = t & 63;
        int nn = nodeBase + r;
        sA[r][c] = (nn < NN) ? g_out1[nn * 64 + c] : 0.f;
    }
    __syncthreads();
    float acc[32];
    #pragma unroll
    for (int r = 0; r < 32; r++) acc[r] = 0.f;
    int j = tid;
    #pragma unroll 2
    for (int k = 0; k < 64; k++) {
        float w = W2[k * 256 + j];
        #pragma unroll
        for (int r = 0; r < 32; r++) acc[r] += sA[r][k] * w;
    }
    float aj_s = a_src[j], aj_d = a_dst[j];
    int lane = tid & 31, wid = tid >> 5;
    #pragma unroll
    for (int r = 0; r < 32; r++) {
        int nn = nodeBase + r;
        if (nn < NN) g_h2[nn * 256 + j] = __float2half_rn(acc[r]);
        float ps = acc[r] * aj_s, pd = acc[r] * aj_d;
        #pragma unroll
        for (int off = 16; off; off >>= 1) {
            ps += __shfl_xor_sync(0xffffffffu, ps, off);
            pd += __shfl_xor_sync(0xffffffffu, pd, off);
        }
        if (lane == 0) { sred[wid][r][0] = ps; sred[wid][r][1] = pd; }
    }
    __syncthreads();
    if (tid < 64) {
        int r = tid >> 1, which = tid & 1;
        int nn = nodeBase + r;
        if (nn < NN) {
            float s = 0.f;
            #pragma unroll
            for (int w = 0; w < 8; w++) s += sred[w][r][which];
            if (which == 0) g_ssrc2[nn] = s;
            else            g_sdst2[nn] = s;
        }
    }
}

// agg2: 32 threads/node (8 fp16 ch each), weight recomputed inline, 2-edge unroll
__global__ void agg2_kernel(const float* __restrict__ b2) {
    int node = blockIdx.x * 8 + (threadIdx.x >> 5);
    int t = threadIdx.x & 31;         // ch = 8t .. 8t+7
    float sd = g_sdst2[node];
    float mx = g_mx2[node];
    float accA[8], accB[8];
    #pragma unroll
    for (int c = 0; c < 8; c++) { accA[c] = 0.f; accB[c] = 0.f; }
    int beg = g_offsets[node], end = g_offsets[node + 1];
    const __half* h2 = g_h2;
    int i = beg;
    for (; i + 1 < end; i += 2) {
        int s0 = g_csr_src[i], s1 = g_csr_src[i + 1];
        float w0 = __expf(leaky(g_ssrc2[s0] + sd) - mx);
        float w1 = __expf(leaky(g_ssrc2[s1] + sd) - mx);
        uint4 r0 = *(const uint4*)(h2 + s0 * 256 + t * 8);
        uint4 r1 = *(const uint4*)(h2 + s1 * 256 + t * 8);
        const __half2* p0 = (const __half2*)&r0;
        const __half2* p1 = (const __half2*)&r1;
        #pragma unroll
        for (int c = 0; c < 4; c++) {
            float2 v0 = __half22float2(p0[c]);
            float2 v1 = __half22float2(p1[c]);
            accA[2 * c]     += w0 * v0.x;  accA[2 * c + 1] += w0 * v0.y;
            accB[2 * c]     += w1 * v1.x;  accB[2 * c + 1] += w1 * v1.y;
        }
    }
    if (i < end) {
        int s0 = g_csr_src[i];
        float w0 = __expf(leaky(g_ssrc2[s0] + sd) - mx);
        uint4 r0 = *(const uint4*)(h2 + s0 * 256 + t * 8);
        const __half2* p0 = (const __half2*)&r0;
        #pragma unroll
        for (int c = 0; c < 4; c++) {
            float2 v0 = __half22float2(p0[c]);
            accA[2 * c]     += w0 * v0.x;  accA[2 * c + 1] += w0 * v0.y;
        }
    }
    float inv = g_inv2[node];
    #pragma unroll
    for (int c = 0; c < 8; c++)
        g_out2[node * 256 + t * 8 + c] = elu((accA[c] + accB[c]) * inv + b2[t * 8 + c]);
}

// ---------------- pool + MLP ------------------------------------------------
__global__ void pool_kernel() {
    int g = blockIdx.x;
    int j = threadIdx.x;
    int start = (g * NN + NG - 1) / NG;
    int end   = ((g + 1) * NN + NG - 1) / NG;
    float mx = -3.4e38f;
    for (int n = start; n < end; n++)
        mx = fmaxf(mx, g_out2[n * 256 + j]);
    g_poolf[g * 256 + j] = mx;
}

__global__ void mlp_tiled_kernel(const float* __restrict__ A, const float* __restrict__ W,
                                 const float* __restrict__ b, float* __restrict__ C,
                                 int K, int Nc, int do_relu) {
    __shared__ float sA[16][64];
    int rowBase = blockIdx.y * 16;
    int j = blockIdx.x * 256 + threadIdx.x;
    float acc[16];
    #pragma unroll
    for (int r = 0; r < 16; r++) acc[r] = 0.f;
    for (int k0 = 0; k0 < K; k0 += 64) {
        for (int t = threadIdx.x; t < 16 * 64; t += 256) {
            int r = t >> 6, c = t & 63;
            sA[r][c] = A[(rowBase + r) * K + k0 + c];
        }
        __syncthreads();
        #pragma unroll 4
        for (int kk = 0; kk < 64; kk++) {
            float w = W[(k0 + kk) * Nc + j];
            #pragma unroll
            for (int r = 0; r < 16; r++) acc[r] += sA[r][kk] * w;
        }
        __syncthreads();
    }
    float bj = b[j];
    #pragma unroll
    for (int r = 0; r < 16; r++) {
        float v = acc[r] + bj;
        if (do_relu) v = fmaxf(v, 0.f);
        C[(rowBase + r) * Nc + j] = v;
    }
}

__global__ void mlp3_kernel(const float* __restrict__ A, const float* __restrict__ W,
                            const float* __restrict__ b, float* __restrict__ C) {
    int g = blockIdx.x;
    int tid = threadIdx.x;
    float acc[4] = {0.f, 0.f, 0.f, 0.f};
    for (int k = tid; k < 1024; k += 256) {
        float a = A[g * 1024 + k];
        #pragma unroll
        for (int jj = 0; jj < 4; jj++) acc[jj] += a * W[k * 4 + jj];
    }
    #pragma unroll
    for (int jj = 0; jj < 4; jj++)
        #pragma unroll
        for (int off = 16; off; off >>= 1)
            acc[jj] += __shfl_xor_sync(0xffffffffu, acc[jj], off);
    __shared__ float red[8][4];
    int lane = tid & 31, wid = tid >> 5;
    if (lane == 0)
        #pragma unroll
        for (int jj = 0; jj < 4; jj++) red[wid][jj] = acc[jj];
    __syncthreads();
    if (tid < 4) {
        float s = b[tid];
        #pragma unroll
        for (int w = 0; w < 8; w++) s += red[w][tid];
        C[g * 4 + tid] = s;
    }
}

// ---------------- launch ----------------------------------------------------
extern "C" void kernel_launch(void* const* d_in, const int* in_sizes, int n_in,
                              void* d_out, int out_size) {
    const float* x      = (const float*)d_in[0];
    const int*   ei     = (const int*)  d_in[1];
    const float* W1     = (const float*)d_in[3];
    const float* a_src1 = (const float*)d_in[4];
    const float* a_dst1 = (const float*)d_in[5];
    const float* b1     = (const float*)d_in[6];
    const float* W2     = (const float*)d_in[7];
    const float* a_src2 = (const float*)d_in[8];
    const float* a_dst2 = (const float*)d_in[9];
    const float* b2     = (const float*)d_in[10];
    const float* Wl1    = (const float*)d_in[11];
    const float* bl1    = (const float*)d_in[12];
    const float* Wl2    = (const float*)d_in[13];
    const float* bl2    = (const float*)d_in[14];
    const float* Wl3    = (const float*)d_in[15];
    const float* bl3    = (const float*)d_in[16];
    float* out = (float*)d_out;
    (void)n_in; (void)in_sizes; (void)out_size;

    float *p_ssrc1, *p_sdst1, *p_mx1, *p_inv1, *p_ssrc2, *p_sdst2, *p_mx2, *p_inv2,
          *p_poolf, *p_z1, *p_z2;
    cudaGetSymbolAddress((void**)&p_ssrc1, g_ssrc1);
    cudaGetSymbolAddress((void**)&p_sdst1, g_sdst1);
    cudaGetSymbolAddress((void**)&p_mx1, g_mx1);
    cudaGetSymbolAddress((void**)&p_inv1, g_inv1);
    cudaGetSymbolAddress((void**)&p_ssrc2, g_ssrc2);
    cudaGetSymbolAddress((void**)&p_sdst2, g_sdst2);
    cudaGetSymbolAddress((void**)&p_mx2, g_mx2);
    cudaGetSymbolAddress((void**)&p_inv2, g_inv2);
    cudaGetSymbolAddress((void**)&p_poolf, g_poolf);
    cudaGetSymbolAddress((void**)&p_z1, g_z1);
    cudaGetSymbolAddress((void**)&p_z2, g_z2);

    // prep
    zero_kernel<<<NB, 256>>>();
    hist_kernel<<<(NET + 255) / 256, 256>>>(ei);
    bsum_kernel<<<NB, 256>>>();
    bscan_kernel<<<1, 256>>>();
    offs_kernel<<<NB, 256>>>();
    scatter_kernel<<<(NET + 255) / 256, 256>>>(ei);

    // layer 1
    gemm1_kernel<<<NN / 4, 256>>>(x, W1, a_src1, a_dst1);
    stats_kernel<4><<<(NN + 7) / 8, 256>>>(p_ssrc1, p_sdst1, p_mx1, p_inv1);
    agg1_kernel<<<(NN + 31) / 32, 256>>>(b1);

    // layer 2
    gemm2_kernel<<<(NN + 31) / 32, 256>>>(W2, a_src2, a_dst2);
    stats_kernel<1><<<(NN + 7) / 8, 256>>>(p_ssrc2, p_sdst2, p_mx2, p_inv2);
    agg2_kernel<<<NN / 8, 256>>>(b2);

    // pool + MLP
    pool_kernel<<<NG, 256>>>();
    dim3 grid1(512 / 256, NG / 16);
    mlp_tiled_kernel<<<grid1, 256>>>(p_poolf, Wl1, bl1, p_z1, 256, 512, 1);
    dim3 grid2(1024 / 256, NG / 16);
    mlp_tiled_kernel<<<grid2, 256>>>(p_z1, Wl2, bl2, p_z2, 512, 1024, 1);
    mlp3_kernel<<<NG, 256>>>(p_z2, Wl3, bl3, out);
}

// round 5
// speedup vs baseline: 1.0002x; 1.0002x over previous
#include <cuda_runtime.h>
#include <cuda_fp16.h>
#include <math.h>

#define NN 50000
#define NE 800000
#define NET (NE + NN)
#define NG 256
#define NB ((NN + 255) / 256)

// ---------------- device scratch ------------------------------------------
__device__ __half   g_h1[NN * 64];
__device__ float    g_ssrc1[NN * 4];
__device__ float    g_sdst1[NN * 4];
__device__ float    g_out1[NN * 64];
__device__ __half   g_h2[NN * 256];
__device__ float    g_ssrc2[NN];
__device__ float    g_sdst2[NN];
__device__ float    g_out2[NN * 256];
__device__ int      g_counts[NN];
__device__ int      g_offsets[NN + 1];
__device__ int      g_bsums[NB];
__device__ int      g_epos[NET];
__device__ int      g_csr_src[NET];
__device__ float    g_csr_w[NET * 4];
__device__ float    g_poolf[NG * 256];
__device__ float    g_z1[NG * 512];
__device__ float    g_z2[NG * 1024];

// ---------------- helpers --------------------------------------------------
__device__ __forceinline__ float leaky(float x) { return x > 0.f ? x : 0.2f * x; }
__device__ __forceinline__ float elu(float x)   { return x > 0.f ? x : expm1f(x); }

// ---------------- prep -----------------------------------------------------
__global__ void zero_kernel() {
    int i = blockIdx.x * blockDim.x + threadIdx.x;
    if (i < NN) g_counts[i] = 0;
}

__global__ void hist_kernel(const int* __restrict__ ei) {
    int e = blockIdx.x * blockDim.x + threadIdx.x;
    if (e >= NET) return;
    int dst = (e < NE) ? ei[NE + e] : (e - NE);
    g_epos[e] = atomicAdd(&g_counts[dst], 1);
}

__global__ void bsum_kernel() {
    __shared__ int ws[8];
    int i = blockIdx.x * 256 + threadIdx.x;
    int v = (i < NN) ? g_counts[i] : 0;
    #pragma unroll
    for (int off = 16; off; off >>= 1) v += __shfl_xor_sync(0xffffffffu, v, off);
    int lane = threadIdx.x & 31, wid = threadIdx.x >> 5;
    if (lane == 0) ws[wid] = v;
    __syncthreads();
    if (threadIdx.x == 0) {
        int s = 0;
        #pragma unroll
        for (int w = 0; w < 8; w++) s += ws[w];
        g_bsums[blockIdx.x] = s;
    }
}

__global__ void bscan_kernel() {
    __shared__ int wsum[8];
    int t = threadIdx.x, lane = t & 31, wid = t >> 5;
    int v = (t < NB) ? g_bsums[t] : 0;
    int s = v;
    #pragma unroll
    for (int off = 1; off < 32; off <<= 1) {
        int u = __shfl_up_sync(0xffffffffu, s, off);
        if (lane >= off) s += u;
    }
    if (lane == 31) wsum[wid] = s;
    __syncthreads();
    if (wid == 0 && lane < 8) {
        int ws = wsum[lane];
        #pragma unroll
        for (int off = 1; off < 8; off <<= 1) {
            int u = __shfl_up_sync(0xffu, ws, off);
            if (lane >= off) ws += u;
        }
        wsum[lane] = ws;
    }
    __syncthreads();
    int pre = (wid > 0) ? wsum[wid - 1] : 0;
    if (t < NB) g_bsums[t] = pre + s - v;
}

__global__ void offs_kernel() {
    __shared__ int wsum[8];
    int t = threadIdx.x, lane = t & 31, wid = t >> 5;
    int i = blockIdx.x * 256 + t;
    int v = (i < NN) ? g_counts[i] : 0;
    int s = v;
    #pragma unroll
    for (int off = 1; off < 32; off <<= 1) {
        int u = __shfl_up_sync(0xffffffffu, s, off);
        if (lane >= off) s += u;
    }
    if (lane == 31) wsum[wid] = s;
    __syncthreads();
    if (wid == 0 && lane < 8) {
        int ws = wsum[lane];
        #pragma unroll
        for (int off = 1; off < 8; off <<= 1) {
            int u = __shfl_up_sync(0xffu, ws, off);
            if (lane >= off) ws += u;
        }
        wsum[lane] = ws;
    }
    __syncthreads();
    int pre = (wid > 0) ? wsum[wid - 1] : 0;
    if (i < NN) g_offsets[i] = g_bsums[blockIdx.x] + pre + s - v;
    if (i == 0) g_offsets[NN] = NET;
}

__global__ void scatter_kernel(const int* __restrict__ ei) {
    int e = blockIdx.x * blockDim.x + threadIdx.x;
    if (e >= NET) return;
    int src, dst;
    if (e < NE) { src = ei[e]; dst = ei[NE + e]; }
    else        { src = dst = e - NE; }
    g_csr_src[g_offsets[dst] + g_epos[e]] = src;
}

// ---------------- GAT layer 1 ----------------------------------------------
// h1 = x @ W1 (fp16 store), fused s1. 4 nodes / 256-thread block.
__global__ void gemm1_kernel(const float* __restrict__ x, const float* __restrict__ W1,
                             const float* __restrict__ a_src, const float* __restrict__ a_dst) {
    __shared__ float sx[4][28];
    int nodeBase = blockIdx.x * 4;
    int tid = threadIdx.x;
    if (tid < 4 * 27) {
        int n = tid / 27, c = tid - n * 27;
        sx[n][c] = x[(nodeBase + n) * 27 + c];
    }
    __syncthreads();
    int n = tid >> 6, j = tid & 63;
    float acc = 0.f;
    #pragma unroll
    for (int k = 0; k < 27; k++) acc += sx[n][k] * W1[k * 64 + j];
    g_h1[(nodeBase + n) * 64 + j] = __float2half_rn(acc);
    float ps = acc * a_src[j];
    float pd = acc * a_dst[j];
    #pragma unroll
    for (int off = 8; off; off >>= 1) {
        ps += __shfl_xor_sync(0xffffffffu, ps, off);
        pd += __shfl_xor_sync(0xffffffffu, pd, off);
    }
    if ((j & 15) == 0) {
        int h = j >> 4;
        g_ssrc1[(nodeBase + n) * 4 + h] = ps;
        g_sdst1[(nodeBase + n) * 4 + h] = pd;
    }
}

// warp per node. Pass A: gather leaky scores -> store, ONLINE (mx, den).
// Pass B: coalesced re-read, write fully normalized weight exp(v-mx)*inv.
template <int H>
__global__ void attn_kernel(const float* __restrict__ ssrc, const float* __restrict__ sdst,
                            float* __restrict__ csr_w) {
    int node = blockIdx.x * 8 + (threadIdx.x >> 5);
    if (node >= NN) return;
    int lane = threadIdx.x & 31;
    int beg = g_offsets[node], end = g_offsets[node + 1];
    float sd[H], mx[H], den[H];
    #pragma unroll
    for (int h = 0; h < H; h++) { sd[h] = sdst[node * H + h]; mx[h] = -3.4e38f; den[h] = 0.f; }

    for (int i = beg + lane; i < end; i += 32) {
        int s = g_csr_src[i];
        if (H == 4) {
            float4 sv = *(const float4*)(ssrc + s * 4);
            float4 v;
            v.x = leaky(sv.x + sd[0]); v.y = leaky(sv.y + sd[1]);
            v.z = leaky(sv.z + sd[2]); v.w = leaky(sv.w + sd[3]);
            *(float4*)(csr_w + i * 4) = v;
            float vv[4] = { v.x, v.y, v.z, v.w };
            #pragma unroll
            for (int h = 0; h < 4; h++) {
                float nm = fmaxf(mx[h], vv[h]);
                den[h] = den[h] * __expf(mx[h] - nm) + __expf(vv[h] - nm);
                mx[h] = nm;
            }
        } else {
            float v = leaky(ssrc[s] + sd[0]);
            csr_w[i] = v;
            float nm = fmaxf(mx[0], v);
            den[0] = den[0] * __expf(mx[0] - nm) + __expf(v - nm);
            mx[0] = nm;
        }
    }
    #pragma unroll
    for (int h = 0; h < H; h++) {
        #pragma unroll
        for (int off = 16; off; off >>= 1) {
            float omx = __shfl_xor_sync(0xffffffffu, mx[h], off);
            float ode = __shfl_xor_sync(0xffffffffu, den[h], off);
            float nm = fmaxf(mx[h], omx);
            den[h] = den[h] * __expf(mx[h] - nm) + ode * __expf(omx - nm);
            mx[h] = nm;
        }
    }
    float inv[H];
    #pragma unroll
    for (int h = 0; h < H; h++) inv[h] = 1.f / (den[h] + 1e-16f);

    for (int i = beg + lane; i < end; i += 32) {
        if (H == 4) {
            float4 v = *(const float4*)(csr_w + i * 4);
            v.x = __expf(v.x - mx[0]) * inv[0];
            v.y = __expf(v.y - mx[1]) * inv[1];
            v.z = __expf(v.z - mx[2]) * inv[2];
            v.w = __expf(v.w - mx[3]) * inv[3];
            *(float4*)(csr_w + i * 4) = v;
        } else {
            csr_w[i] = __expf(csr_w[i] - mx[0]) * inv[0];
        }
    }
}

// agg1: 8 threads/node (8 fp16 ch each), normalized w loaded, 2-edge unroll
__global__ void agg1_kernel(const float* __restrict__ b1) {
    int node = blockIdx.x * 32 + (threadIdx.x >> 3);
    if (node >= NN) return;
    int t = threadIdx.x & 7;
    int h = t >> 1;
    float accA[8], accB[8];
    #pragma unroll
    for (int c = 0; c < 8; c++) { accA[c] = 0.f; accB[c] = 0.f; }
    int beg = g_offsets[node], end = g_offsets[node + 1];
    const __half* h1 = g_h1;
    int i = beg;
    for (; i + 1 < end; i += 2) {
        int s0 = g_csr_src[i], s1 = g_csr_src[i + 1];
        float w0 = g_csr_w[i * 4 + h];
        float w1 = g_csr_w[(i + 1) * 4 + h];
        uint4 r0 = *(const uint4*)(h1 + s0 * 64 + t * 8);
        uint4 r1 = *(const uint4*)(h1 + s1 * 64 + t * 8);
        const __half2* p0 = (const __half2*)&r0;
        const __half2* p1 = (const __half2*)&r1;
        #pragma unroll
        for (int c = 0; c < 4; c++) {
            float2 v0 = __half22float2(p0[c]);
            float2 v1 = __half22float2(p1[c]);
            accA[2 * c]     += w0 * v0.x;  accA[2 * c + 1] += w0 * v0.y;
            accB[2 * c]     += w1 * v1.x;  accB[2 * c + 1] += w1 * v1.y;
        }
    }
    if (i < end) {
        int s0 = g_csr_src[i];
        float w0 = g_csr_w[i * 4 + h];
        uint4 r0 = *(const uint4*)(h1 + s0 * 64 + t * 8);
        const __half2* p0 = (const __half2*)&r0;
        #pragma unroll
        for (int c = 0; c < 4; c++) {
            float2 v0 = __half22float2(p0[c]);
            accA[2 * c]     += w0 * v0.x;  accA[2 * c + 1] += w0 * v0.y;
        }
    }
    #pragma unroll
    for (int c = 0; c < 8; c++)
        g_out1[node * 64 + t * 8 + c] = elu(accA[c] + accB[c] + b1[t * 8 + c]);
}

// ---------------- GAT layer 2 ----------------------------------------------
// h2 = out1 @ W2 -> fp16; s2 fused. 32 rows / 256-thread block.
__global__ void gemm2_kernel(const float* __restrict__ W2,
                             const float* __restrict__ a_src, const float* __restrict__ a_dst) {
    __shared__ float sA[32][64];
    __shared__ float sred[8][32][2];
    int nodeBase = blockIdx.x * 32;
    int tid = threadIdx.x;
    for (int t = tid; t < 32 * 64; t += 256) {
        int r = t >> 6, c = t & 63;
        int nn = nodeBase + r;
        sA[r][c] = (nn < NN) ? g_out1[nn * 64 + c] : 0.f;
    }
    __syncthreads();
    float acc[32];
    #pragma unroll
    for (int r = 0; r < 32; r++) acc[r] = 0.f;
    int j = tid;
    #pragma unroll 2
    for (int k = 0; k < 64; k++) {
        float w = W2[k * 256 + j];
        #pragma unroll
        for (int r = 0; r < 32; r++) acc[r] += sA[r][k] * w;
    }
    float aj_s = a_src[j], aj_d = a_dst[j];
    int lane = tid & 31, wid = tid >> 5;
    #pragma unroll
    for (int r = 0; r < 32; r++) {
        int nn = nodeBase + r;
        if (nn < NN) g_h2[nn * 256 + j] = __float2half_rn(acc[r]);
        float ps = acc[r] * aj_s, pd = acc[r] * aj_d;
        #pragma unroll
        for (int off = 16; off; off >>= 1) {
            ps += __shfl_xor_sync(0xffffffffu, ps, off);
            pd += __shfl_xor_sync(0xffffffffu, pd, off);
        }
        if (lane == 0) { sred[wid][r][0] = ps; sred[wid][r][1] = pd; }
    }
    __syncthreads();
    if (tid < 64) {
        int r = tid >> 1, which = tid & 1;
        int nn = nodeBase + r;
        if (nn < NN) {
            float s = 0.f;
            #pragma unroll
            for (int w = 0; w < 8; w++) s += sred[w][r][which];
            if (which == 0) g_ssrc2[nn] = s;
            else            g_sdst2[nn] = s;
        }
    }
}

// agg2: 32 threads/node (8 fp16 ch each), normalized w loaded, 2-edge unroll
__global__ void agg2_kernel(const float* __restrict__ b2) {
    int node = blockIdx.x * 8 + (threadIdx.x >> 5);
    int t = threadIdx.x & 31;
    float accA[8], accB[8];
    #pragma unroll
    for (int c = 0; c < 8; c++) { accA[c] = 0.f; accB[c] = 0.f; }
    int beg = g_offsets[node], end = g_offsets[node + 1];
    const __half* h2 = g_h2;
    int i = beg;
    for (; i + 1 < end; i += 2) {
        int s0 = g_csr_src[i], s1 = g_csr_src[i + 1];
        float w0 = g_csr_w[i];
        float w1 = g_csr_w[i + 1];
        uint4 r0 = *(const uint4*)(h2 + s0 * 256 + t * 8);
        uint4 r1 = *(const uint4*)(h2 + s1 * 256 + t * 8);
        const __half2* p0 = (const __half2*)&r0;
        const __half2* p1 = (const __half2*)&r1;
        #pragma unroll
        for (int c = 0; c < 4; c++) {
            float2 v0 = __half22float2(p0[c]);
            float2 v1 = __half22float2(p1[c]);
            accA[2 * c]     += w0 * v0.x;  accA[2 * c + 1] += w0 * v0.y;
            accB[2 * c]     += w1 * v1.x;  accB[2 * c + 1] += w1 * v1.y;
        }
    }
    if (i < end) {
        int s0 = g_csr_src[i];
        float w0 = g_csr_w[i];
        uint4 r0 = *(const uint4*)(h2 + s0 * 256 + t * 8);
        const __half2* p0 = (const __half2*)&r0;
        #pragma unroll
        for (int c = 0; c < 4; c++) {
            float2 v0 = __half22float2(p0[c]);
            accA[2 * c]     += w0 * v0.x;  accA[2 * c + 1] += w0 * v0.y;
        }
    }
    #pragma unroll
    for (int c = 0; c < 8; c++)
        g_out2[node * 256 + t * 8 + c] = elu(accA[c] + accB[c] + b2[t * 8 + c]);
}

// ---------------- pool + MLP ------------------------------------------------
__global__ void pool_kernel() {
    int g = blockIdx.x;
    int j = threadIdx.x;
    int start = (g * NN + NG - 1) / NG;
    int end   = ((g + 1) * NN + NG - 1) / NG;
    float mx = -3.4e38f;
    for (int n = start; n < end; n++)
        mx = fmaxf(mx, g_out2[n * 256 + j]);
    g_poolf[g * 256 + j] = mx;
}

__global__ void mlp_tiled_kernel(const float* __restrict__ A, const float* __restrict__ W,
                                 const float* __restrict__ b, float* __restrict__ C,
                                 int K, int Nc, int do_relu) {
    __shared__ float sA[16][64];
    int rowBase = blockIdx.y * 16;
    int j = blockIdx.x * 256 + threadIdx.x;
    float acc[16];
    #pragma unroll
    for (int r = 0; r < 16; r++) acc[r] = 0.f;
    for (int k0 = 0; k0 < K; k0 += 64) {
        for (int t = threadIdx.x; t < 16 * 64; t += 256) {
            int r = t >> 6, c = t & 63;
            sA[r][c] = A[(rowBase + r) * K + k0 + c];
        }
        __syncthreads();
        #pragma unroll 4
        for (int kk = 0; kk < 64; kk++) {
            float w = W[(k0 + kk) * Nc + j];
            #pragma unroll
            for (int r = 0; r < 16; r++) acc[r] += sA[r][kk] * w;
        }
        __syncthreads();
    }
    float bj = b[j];
    #pragma unroll
    for (int r = 0; r < 16; r++) {
        float v = acc[r] + bj;
        if (do_relu) v = fmaxf(v, 0.f);
        C[(rowBase + r) * Nc + j] = v;
    }
}

__global__ void mlp3_kernel(const float* __restrict__ A, const float* __restrict__ W,
                            const float* __restrict__ b, float* __restrict__ C) {
    int g = blockIdx.x;
    int tid = threadIdx.x;
    float acc[4] = {0.f, 0.f, 0.f, 0.f};
    for (int k = tid; k < 1024; k += 256) {
        float a = A[g * 1024 + k];
        #pragma unroll
        for (int jj = 0; jj < 4; jj++) acc[jj] += a * W[k * 4 + jj];
    }
    #pragma unroll
    for (int jj = 0; jj < 4; jj++)
        #pragma unroll
        for (int off = 16; off; off >>= 1)
            acc[jj] += __shfl_xor_sync(0xffffffffu, acc[jj], off);
    __shared__ float red[8][4];
    int lane = tid & 31, wid = tid >> 5;
    if (lane == 0)
        #pragma unroll
        for (int jj = 0; jj < 4; jj++) red[wid][jj] = acc[jj];
    __syncthreads();
    if (tid < 4) {
        float s = b[tid];
        #pragma unroll
        for (int w = 0; w < 8; w++) s += red[w][tid];
        C[g * 4 + tid] = s;
    }
}

// ---------------- launch ----------------------------------------------------
extern "C" void kernel_launch(void* const* d_in, const int* in_sizes, int n_in,
                              void* d_out, int out_size) {
    const float* x      = (const float*)d_in[0];
    const int*   ei     = (const int*)  d_in[1];
    const float* W1     = (const float*)d_in[3];
    const float* a_src1 = (const float*)d_in[4];
    const float* a_dst1 = (const float*)d_in[5];
    const float* b1     = (const float*)d_in[6];
    const float* W2     = (const float*)d_in[7];
    const float* a_src2 = (const float*)d_in[8];
    const float* a_dst2 = (const float*)d_in[9];
    const float* b2     = (const float*)d_in[10];
    const float* Wl1    = (const float*)d_in[11];
    const float* bl1    = (const float*)d_in[12];
    const float* Wl2    = (const float*)d_in[13];
    const float* bl2    = (const float*)d_in[14];
    const float* Wl3    = (const float*)d_in[15];
    const float* bl3    = (const float*)d_in[16];
    float* out = (float*)d_out;
    (void)n_in; (void)in_sizes; (void)out_size;

    float *p_ssrc1, *p_sdst1, *p_ssrc2, *p_sdst2, *p_csr_w, *p_poolf, *p_z1, *p_z2;
    cudaGetSymbolAddress((void**)&p_ssrc1, g_ssrc1);
    cudaGetSymbolAddress((void**)&p_sdst1, g_sdst1);
    cudaGetSymbolAddress((void**)&p_ssrc2, g_ssrc2);
    cudaGetSymbolAddress((void**)&p_sdst2, g_sdst2);
    cudaGetSymbolAddress((void**)&p_csr_w, g_csr_w);
    cudaGetSymbolAddress((void**)&p_poolf, g_poolf);
    cudaGetSymbolAddress((void**)&p_z1, g_z1);
    cudaGetSymbolAddress((void**)&p_z2, g_z2);

    // prep
    zero_kernel<<<NB, 256>>>();
    hist_kernel<<<(NET + 255) / 256, 256>>>(ei);
    bsum_kernel<<<NB, 256>>>();
    bscan_kernel<<<1, 256>>>();
    offs_kernel<<<NB, 256>>>();
    scatter_kernel<<<(NET + 255) / 256, 256>>>(ei);

    // layer 1
    gemm1_kernel<<<NN / 4, 256>>>(x, W1, a_src1, a_dst1);
    attn_kernel<4><<<(NN + 7) / 8, 256>>>(p_ssrc1, p_sdst1, p_csr_w);
    agg1_kernel<<<(NN + 31) / 32, 256>>>(b1);

    // layer 2
    gemm2_kernel<<<(NN + 31) / 32, 256>>>(W2, a_src2, a_dst2);
    attn_kernel<1><<<(NN + 7) / 8, 256>>>(p_ssrc2, p_sdst2, p_csr_w);
    agg2_kernel<<<NN / 8, 256>>>(b2);

    // pool + MLP
    pool_kernel<<<NG, 256>>>();
    dim3 grid1(512 / 256, NG / 16);
    mlp_tiled_kernel<<<grid1, 256>>>(p_poolf, Wl1, bl1, p_z1, 256, 512, 1);
    dim3 grid2(1024 / 256, NG / 16);
    mlp_tiled_kernel<<<grid2, 256>>>(p_z1, Wl2, bl2, p_z2, 512, 1024, 1);
    mlp3_kernel<<<NG, 256>>>(p_z2, Wl3, bl3, out);
}

// round 7
// speedup vs baseline: 1.0507x; 1.0505x over previous
#include <cuda_runtime.h>
#include <cuda_fp16.h>
#include <math.h>

#define NN 50000
#define NE 800000
#define NET (NE + NN)
#define NG 256
#define NB ((NN + 255) / 256)

// ---------------- device scratch ------------------------------------------
__device__ __half   g_h1[NN * 64];
__device__ float    g_ssrc1[NN * 4];
__device__ float    g_sdst1[NN * 4];
__device__ float    g_inv1[NN * 4];
__device__ float    g_out1[NN * 64];
__device__ __half   g_h2[NN * 256];
__device__ float    g_ssrc2[NN];
__device__ float    g_sdst2[NN];
__device__ float    g_inv2[NN];
__device__ float    g_out2[NN * 256];
__device__ int      g_counts[NN];
__device__ int      g_offsets[NN + 1];
__device__ int      g_bsums[NB];
__device__ int      g_epos[NET];
__device__ int      g_csr_src[NET];
__device__ float    g_csr_w[NET * 4];
__device__ float    g_poolf[NG * 256];
__device__ float    g_z1[NG * 512];
__device__ float    g_z2[NG * 1024];

// ---------------- helpers --------------------------------------------------
__device__ __forceinline__ float leaky(float x) { return x > 0.f ? x : 0.2f * x; }
__device__ __forceinline__ float elu(float x)   { return x > 0.f ? x : expm1f(x); }

// ---------------- prep -----------------------------------------------------
__global__ void zero_kernel() {
    int i = blockIdx.x * blockDim.x + threadIdx.x;
    if (i < NN) g_counts[i] = 0;
}

// histogram + intra-bucket position (scatter then needs no atomics)
__global__ void hist_kernel(const int* __restrict__ ei) {
    int e = blockIdx.x * blockDim.x + threadIdx.x;
    if (e >= NET) return;
    int dst = (e < NE) ? ei[NE + e] : (e - NE);
    g_epos[e] = atomicAdd(&g_counts[dst], 1);
}

__global__ void bsum_kernel() {
    __shared__ int ws[8];
    int i = blockIdx.x * 256 + threadIdx.x;
    int v = (i < NN) ? g_counts[i] : 0;
    #pragma unroll
    for (int off = 16; off; off >>= 1) v += __shfl_xor_sync(0xffffffffu, v, off);
    int lane = threadIdx.x & 31, wid = threadIdx.x >> 5;
    if (lane == 0) ws[wid] = v;
    __syncthreads();
    if (threadIdx.x == 0) {
        int s = 0;
        #pragma unroll
        for (int w = 0; w < 8; w++) s += ws[w];
        g_bsums[blockIdx.x] = s;
    }
}

__global__ void bscan_kernel() {
    __shared__ int wsum[8];
    int t = threadIdx.x, lane = t & 31, wid = t >> 5;
    int v = (t < NB) ? g_bsums[t] : 0;
    int s = v;
    #pragma unroll
    for (int off = 1; off < 32; off <<= 1) {
        int u = __shfl_up_sync(0xffffffffu, s, off);
        if (lane >= off) s += u;
    }
    if (lane == 31) wsum[wid] = s;
    __syncthreads();
    if (wid == 0 && lane < 8) {
        int ws = wsum[lane];
        #pragma unroll
        for (int off = 1; off < 8; off <<= 1) {
            int u = __shfl_up_sync(0xffu, ws, off);
            if (lane >= off) ws += u;
        }
        wsum[lane] = ws;
    }
    __syncthreads();
    int pre = (wid > 0) ? wsum[wid - 1] : 0;
    if (t < NB) g_bsums[t] = pre + s - v;
}

__global__ void offs_kernel() {
    __shared__ int wsum[8];
    int t = threadIdx.x, lane = t & 31, wid = t >> 5;
    int i = blockIdx.x * 256 + t;
    int v = (i < NN) ? g_counts[i] : 0;
    int s = v;
    #pragma unroll
    for (int off = 1; off < 32; off <<= 1) {
        int u = __shfl_up_sync(0xffffffffu, s, off);
        if (lane >= off) s += u;
    }
    if (lane == 31) wsum[wid] = s;
    __syncthreads();
    if (wid == 0 && lane < 8) {
        int ws = wsum[lane];
        #pragma unroll
        for (int off = 1; off < 8; off <<= 1) {
            int u = __shfl_up_sync(0xffu, ws, off);
            if (lane >= off) ws += u;
        }
        wsum[lane] = ws;
    }
    __syncthreads();
    int pre = (wid > 0) ? wsum[wid - 1] : 0;
    if (i < NN) g_offsets[i] = g_bsums[blockIdx.x] + pre + s - v;
    if (i == 0) g_offsets[NN] = NET;
}

__global__ void scatter_kernel(const int* __restrict__ ei) {
    int e = blockIdx.x * blockDim.x + threadIdx.x;
    if (e >= NET) return;
    int src, dst;
    if (e < NE) { src = ei[e]; dst = ei[NE + e]; }
    else        { src = dst = e - NE; }
    g_csr_src[g_offsets[dst] + g_epos[e]] = src;
}

// ---------------- GAT layer 1 ----------------------------------------------
// h1 = x @ W1 (fp16 store), fused s1 (16-lane butterfly per head)
__global__ void gemm1_kernel(const float* __restrict__ x, const float* __restrict__ W1,
                             const float* __restrict__ a_src, const float* __restrict__ a_dst) {
    int idx = blockIdx.x * blockDim.x + threadIdx.x;   // NN*64 exact
    int n = idx >> 6, j = idx & 63;
    const float* xr = x + n * 27;
    float acc = 0.f;
    #pragma unroll
    for (int k = 0; k < 27; k++) acc += xr[k] * W1[k * 64 + j];
    g_h1[idx] = __float2half_rn(acc);
    float ps = acc * a_src[j];
    float pd = acc * a_dst[j];
    #pragma unroll
    for (int off = 8; off; off >>= 1) {
        ps += __shfl_xor_sync(0xffffffffu, ps, off);
        pd += __shfl_xor_sync(0xffffffffu, pd, off);
    }
    if ((j & 15) == 0) {
        int h = j >> 4;
        g_ssrc1[n * 4 + h] = ps;
        g_sdst1[n * 4 + h] = pd;
    }
}

// warp per node, R2-proven 2-pass: A) gather leaky scores -> store + max;
// B) coalesced exp + sum -> store exp. inv stored per node (agg epilogue).
template <int H>
__global__ void attn_kernel(const float* __restrict__ ssrc, const float* __restrict__ sdst,
                            float* __restrict__ csr_w, float* __restrict__ ginv) {
    int node = blockIdx.x * 8 + (threadIdx.x >> 5);
    if (node >= NN) return;
    int lane = threadIdx.x & 31;
    int beg = g_offsets[node], end = g_offsets[node + 1];
    float sd[H];
    #pragma unroll
    for (int h = 0; h < H; h++) sd[h] = sdst[node * H + h];

    float mx[H];
    #pragma unroll
    for (int h = 0; h < H; h++) mx[h] = -3.4e38f;
    for (int i = beg + lane; i < end; i += 32) {
        int s = g_csr_src[i];
        if (H == 4) {
            float4 sv = *(const float4*)(ssrc + s * 4);
            float4 v;
            v.x = leaky(sv.x + sd[0]); v.y = leaky(sv.y + sd[1]);
            v.z = leaky(sv.z + sd[2]); v.w = leaky(sv.w + sd[3]);
            *(float4*)(csr_w + i * 4) = v;
            mx[0] = fmaxf(mx[0], v.x); mx[1] = fmaxf(mx[1], v.y);
            mx[2] = fmaxf(mx[2], v.z); mx[3] = fmaxf(mx[3], v.w);
        } else {
            float v = leaky(ssrc[s] + sd[0]);
            csr_w[i] = v;
            mx[0] = fmaxf(mx[0], v);
        }
    }
    #pragma unroll
    for (int h = 0; h < H; h++)
        #pragma unroll
        for (int off = 16; off; off >>= 1)
            mx[h] = fmaxf(mx[h], __shfl_xor_sync(0xffffffffu, mx[h], off));

    float den[H];
    #pragma unroll
    for (int h = 0; h < H; h++) den[h] = 0.f;
    for (int i = beg + lane; i < end; i += 32) {
        if (H == 4) {
            float4 v = *(const float4*)(csr_w + i * 4);
            v.x = __expf(v.x - mx[0]); v.y = __expf(v.y - mx[1]);
            v.z = __expf(v.z - mx[2]); v.w = __expf(v.w - mx[3]);
            *(float4*)(csr_w + i * 4) = v;
            den[0] += v.x; den[1] += v.y; den[2] += v.z; den[3] += v.w;
        } else {
            float e = __expf(csr_w[i] - mx[0]);
            csr_w[i] = e;
            den[0] += e;
        }
    }
    #pragma unroll
    for (int h = 0; h < H; h++)
        #pragma unroll
        for (int off = 16; off; off >>= 1)
            den[h] += __shfl_xor_sync(0xffffffffu, den[h], off);
    if (lane == 0)
        #pragma unroll
        for (int h = 0; h < H; h++)
            ginv[node * H + h] = 1.f / (den[h] + 1e-16f);
}

// agg1: 16 threads/node (4 fp16 ch each via uint2), 16 nodes/block — R2 layout
__global__ void agg1_kernel(const float* __restrict__ b1) {
    int node = blockIdx.x * 16 + (threadIdx.x >> 4);
    int t = threadIdx.x & 15;        // ch = 4t .. 4t+3
    int h = t >> 2;                  // head
    float acc0 = 0.f, acc1 = 0.f, acc2 = 0.f, acc3 = 0.f;
    int beg = g_offsets[node], end = g_offsets[node + 1];
    const __half* h1 = g_h1;
    for (int i = beg; i < end; i++) {
        int s = g_csr_src[i];
        float w = g_csr_w[i * 4 + h];
        uint2 raw = *(const uint2*)(h1 + s * 64 + t * 4);
        float2 v0 = __half22float2(*(const __half2*)&raw.x);
        float2 v1 = __half22float2(*(const __half2*)&raw.y);
        acc0 += w * v0.x; acc1 += w * v0.y; acc2 += w * v1.x; acc3 += w * v1.y;
    }
    float inv = g_inv1[node * 4 + h];
    float4 bb = *(const float4*)(b1 + t * 4);
    float4 o;
    o.x = elu(acc0 * inv + bb.x);
    o.y = elu(acc1 * inv + bb.y);
    o.z = elu(acc2 * inv + bb.z);
    o.w = elu(acc3 * inv + bb.w);
    *(float4*)(g_out1 + node * 64 + t * 4) = o;
}

// ---------------- GAT layer 2 ----------------------------------------------
// h2 = out1 @ W2 -> fp16; s2 fused. 16 rows / 256-thread block (R2 tile).
__global__ void gemm2_kernel(const float* __restrict__ W2,
                             const float* __restrict__ a_src, const float* __restrict__ a_dst) {
    __shared__ float sA[16][64];
    __shared__ float sred[8][16][2];
    int nodeBase = blockIdx.x * 16;          // 3125 blocks, exact
    int tid = threadIdx.x;
    for (int t = tid; t < 16 * 64; t += 256) {
        int r = t >> 6, c = t & 63;
        sA[r][c] = g_out1[(nodeBase + r) * 64 + c];
    }
    __syncthreads();
    float acc[16];
    #pragma unroll
    for (int r = 0; r < 16; r++) acc[r] = 0.f;
    int j = tid;
    #pragma unroll 4
    for (int k = 0; k < 64; k++) {
        float w = W2[k * 256 + j];
        #pragma unroll
        for (int r = 0; r < 16; r++) acc[r] += sA[r][k] * w;
    }
    float aj_s = a_src[j], aj_d = a_dst[j];
    int lane = tid & 31, wid = tid >> 5;
    #pragma unroll
    for (int r = 0; r < 16; r++) {
        g_h2[(nodeBase + r) * 256 + j] = __float2half_rn(acc[r]);
        float ps = acc[r] * aj_s, pd = acc[r] * aj_d;
        #pragma unroll
        for (int off = 16; off; off >>= 1) {
            ps += __shfl_xor_sync(0xffffffffu, ps, off);
            pd += __shfl_xor_sync(0xffffffffu, pd, off);
        }
        if (lane == 0) { sred[wid][r][0] = ps; sred[wid][r][1] = pd; }
    }
    __syncthreads();
    if (tid < 32) {
        int r = tid >> 1, which = tid & 1;
        float s = 0.f;
        #pragma unroll
        for (int w = 0; w < 8; w++) s += sred[w][r][which];
        if (which == 0) g_ssrc2[nodeBase + r] = s;
        else            g_sdst2[nodeBase + r] = s;
    }
}

// agg2: 32 threads/node (8 fp16 ch each via uint4), 8 nodes/block — R2 layout
__global__ void agg2_kernel(const float* __restrict__ b2) {
    int node = blockIdx.x * 8 + (threadIdx.x >> 5);
    int t = threadIdx.x & 31;        // ch = 8t .. 8t+7
    float acc[8];
    #pragma unroll
    for (int c = 0; c < 8; c++) acc[c] = 0.f;
    int beg = g_offsets[node], end = g_offsets[node + 1];
    const __half* h2 = g_h2;
    for (int i = beg; i < end; i++) {
        int s = g_csr_src[i];
        float w = g_csr_w[i];
        uint4 raw = *(const uint4*)(h2 + s * 256 + t * 8);
        const __half2* hp = (const __half2*)&raw;
        #pragma unroll
        for (int c = 0; c < 4; c++) {
            float2 v = __half22float2(hp[c]);
            acc[2 * c]     += w * v.x;
            acc[2 * c + 1] += w * v.y;
        }
    }
    float inv = g_inv2[node];
    #pragma unroll
    for (int c = 0; c < 8; c++)
        g_out2[node * 256 + t * 8 + c] = elu(acc[c] * inv + b2[t * 8 + c]);
}

// ---------------- pool + MLP ------------------------------------------------
__global__ void pool_kernel() {
    int g = blockIdx.x;
    int j = threadIdx.x;
    int start = (g * NN + NG - 1) / NG;
    int end   = ((g + 1) * NN + NG - 1) / NG;
    float mx = -3.4e38f;
    for (int n = start; n < end; n++)
        mx = fmaxf(mx, g_out2[n * 256 + j]);
    g_poolf[g * 256 + j] = mx;
}

__global__ void mlp_tiled_kernel(const float* __restrict__ A, const float* __restrict__ W,
                                 const float* __restrict__ b, float* __restrict__ C,
                                 int K, int Nc, int do_relu) {
    __shared__ float sA[16][64];
    int rowBase = blockIdx.y * 16;
    int j = blockIdx.x * 256 + threadIdx.x;
    float acc[16];
    #pragma unroll
    for (int r = 0; r < 16; r++) acc[r] = 0.f;
    for (int k0 = 0; k0 < K; k0 += 64) {
        for (int t = threadIdx.x; t < 16 * 64; t += 256) {
            int r = t >> 6, c = t & 63;
            sA[r][c] = A[(rowBase + r) * K + k0 + c];
        }
        __syncthreads();
        #pragma unroll 4
        for (int kk = 0; kk < 64; kk++) {
            float w = W[(k0 + kk) * Nc + j];
            #pragma unroll
            for (int r = 0; r < 16; r++) acc[r] += sA[r][kk] * w;
        }
        __syncthreads();
    }
    float bj = b[j];
    #pragma unroll
    for (int r = 0; r < 16; r++) {
        float v = acc[r] + bj;
        if (do_relu) v = fmaxf(v, 0.f);
        C[(rowBase + r) * Nc + j] = v;
    }
}

__global__ void mlp3_kernel(const float* __restrict__ A, const float* __restrict__ W,
                            const float* __restrict__ b, float* __restrict__ C) {
    int g = blockIdx.x;
    int tid = threadIdx.x;
    float acc[4] = {0.f, 0.f, 0.f, 0.f};
    for (int k = tid; k < 1024; k += 256) {
        float a = A[g * 1024 + k];
        #pragma unroll
        for (int jj = 0; jj < 4; jj++) acc[jj] += a * W[k * 4 + jj];
    }
    #pragma unroll
    for (int jj = 0; jj < 4; jj++)
        #pragma unroll
        for (int off = 16; off; off >>= 1)
            acc[jj] += __shfl_xor_sync(0xffffffffu, acc[jj], off);
    __shared__ float red[8][4];
    int lane = tid & 31, wid = tid >> 5;
    if (lane == 0)
        #pragma unroll
        for (int jj = 0; jj < 4; jj++) red[wid][jj] = acc[jj];
    __syncthreads();
    if (tid < 4) {
        float s = b[tid];
        #pragma unroll
        for (int w = 0; w < 8; w++) s += red[w][tid];
        C[g * 4 + tid] = s;
    }
}

// ---------------- launch ----------------------------------------------------
extern "C" void kernel_launch(void* const* d_in, const int* in_sizes, int n_in,
                              void* d_out, int out_size) {
    const float* x      = (const float*)d_in[0];
    const int*   ei     = (const int*)  d_in[1];
    const float* W1     = (const float*)d_in[3];
    const float* a_src1 = (const float*)d_in[4];
    const float* a_dst1 = (const float*)d_in[5];
    const float* b1     = (const float*)d_in[6];
    const float* W2     = (const float*)d_in[7];
    const float* a_src2 = (const float*)d_in[8];
    const float* a_dst2 = (const float*)d_in[9];
    const float* b2     = (const float*)d_in[10];
    const float* Wl1    = (const float*)d_in[11];
    const float* bl1    = (const float*)d_in[12];
    const float* Wl2    = (const float*)d_in[13];
    const float* bl2    = (const float*)d_in[14];
    const float* Wl3    = (const float*)d_in[15];
    const float* bl3    = (const float*)d_in[16];
    float* out = (float*)d_out;
    (void)n_in; (void)in_sizes; (void)out_size;

    float *p_ssrc1, *p_sdst1, *p_inv1, *p_ssrc2, *p_sdst2, *p_inv2,
          *p_csr_w, *p_poolf, *p_z1, *p_z2;
    cudaGetSymbolAddress((void**)&p_ssrc1, g_ssrc1);
    cudaGetSymbolAddress((void**)&p_sdst1, g_sdst1);
    cudaGetSymbolAddress((void**)&p_inv1, g_inv1);
    cudaGetSymbolAddress((void**)&p_ssrc2, g_ssrc2);
    cudaGetSymbolAddress((void**)&p_sdst2, g_sdst2);
    cudaGetSymbolAddress((void**)&p_inv2, g_inv2);
    cudaGetSymbolAddress((void**)&p_csr_w, g_csr_w);
    cudaGetSymbolAddress((void**)&p_poolf, g_poolf);
    cudaGetSymbolAddress((void**)&p_z1, g_z1);
    cudaGetSymbolAddress((void**)&p_z2, g_z2);

    // prep
    zero_kernel<<<NB, 256>>>();
    hist_kernel<<<(NET + 255) / 256, 256>>>(ei);
    bsum_kernel<<<NB, 256>>>();
    bscan_kernel<<<1, 256>>>();
    offs_kernel<<<NB, 256>>>();
    scatter_kernel<<<(NET + 255) / 256, 256>>>(ei);

    // layer 1
    gemm1_kernel<<<NN * 64 / 256, 256>>>(x, W1, a_src1, a_dst1);
    attn_kernel<4><<<(NN + 7) / 8, 256>>>(p_ssrc1, p_sdst1, p_csr_w, p_inv1);
    agg1_kernel<<<NN / 16, 256>>>(b1);

    // layer 2
    gemm2_kernel<<<NN / 16, 256>>>(W2, a_src2, a_dst2);
    attn_kernel<1><<<(NN + 7) / 8, 256>>>(p_ssrc2, p_sdst2, p_csr_w, p_inv2);
    agg2_kernel<<<NN / 8, 256>>>(b2);

    // pool + MLP
    pool_kernel<<<NG, 256>>>();
    dim3 grid1(512 / 256, NG / 16);
    mlp_tiled_kernel<<<grid1, 256>>>(p_poolf, Wl1, bl1, p_z1, 256, 512, 1);
    dim3 grid2(1024 / 256, NG / 16);
    mlp_tiled_kernel<<<grid2, 256>>>(p_z1, Wl2, bl2, p_z2, 512, 1024, 1);
    mlp3_kernel<<<NG, 256>>>(p_z2, Wl3, bl3, out);
}